// round 1
// baseline (speedup 1.0000x reference)
#include <cuda_runtime.h>
#include <math.h>

#define NV 5
#define HIMG 512
#define WIMG 640
#define CFE 32
#define ND 128
#define HFE 64
#define WFE 80
#define H1 256
#define W1 320
#define H2 128
#define W2 160

// ---------------- scratch (device globals, no allocation) ----------------
__device__ float g_e1[NV*8*H1*W1];
__device__ float g_e2[NV*16*H2*W2];
__device__ float g_feats[NV*HFE*WFE*CFE];     // channel-last (v,y,x,c)
__device__ float g_cost[CFE*ND*HFE*WFE];      // (c,d,y,x)
__device__ float g_reg1[8*ND*HFE*WFE];        // (oc,d,y,x)
__device__ float g_cost2[ND*HFE*WFE];         // (d,y,x)
__device__ float g_conf[HFE*WFE];
__device__ float g_regd[HFE*WFE];
__device__ float g_regup[HIMG*WIMG];
__device__ float g_hidden[HIMG*WIMG*32];      // channel-last (y,x,c)
__device__ float g_Hm[4*9];
__device__ float g_bb[4*3];
__device__ float g_depths[ND];

// ---------------- setup: depths + homographies ----------------
__global__ void setup_kernel(const float* __restrict__ K, const float* __restrict__ poses) {
    for (int i = 0; i < ND; i++) {
        float inv = 2.0f + (float)i * (0.2f - 2.0f) / 127.0f;
        g_depths[i] = 1.0f / inv;
    }
    float fx = K[0] / 8.0f, cx = K[2] / 8.0f, fy = K[4] / 8.0f, cy = K[5] / 8.0f;
    float Kf[9] = {fx, 0, cx, 0, fy, cy, 0, 0, 1};
    float Ki[9] = {1.0f/fx, 0, -cx/fx, 0, 1.0f/fy, -cy/fy, 0, 0, 1};
    // rigid inverse of poses[0]
    float R0T[9], ti[3];
    for (int r = 0; r < 3; r++)
        for (int c = 0; c < 3; c++) R0T[r*3+c] = poses[c*4+r];
    for (int r = 0; r < 3; r++) {
        float s = 0;
        for (int c = 0; c < 3; c++) s += R0T[r*3+c] * poses[c*4+3];
        ti[r] = -s;
    }
    for (int v = 1; v < NV; v++) {
        const float* P = poses + v*16;
        float Rt[9], tt[3], A[9];
        for (int r = 0; r < 3; r++)
            for (int c = 0; c < 3; c++) {
                float s = 0;
                for (int k = 0; k < 3; k++) s += P[r*4+k] * R0T[k*3+c];
                Rt[r*3+c] = s;
            }
        for (int r = 0; r < 3; r++) {
            float s = 0;
            for (int k = 0; k < 3; k++) s += P[r*4+k] * ti[k];
            tt[r] = s + P[r*4+3];
        }
        for (int r = 0; r < 3; r++)
            for (int c = 0; c < 3; c++) {
                float s = 0;
                for (int k = 0; k < 3; k++) s += Kf[r*3+k] * Rt[k*3+c];
                A[r*3+c] = s;
            }
        for (int r = 0; r < 3; r++)
            for (int c = 0; c < 3; c++) {
                float s = 0;
                for (int k = 0; k < 3; k++) s += A[r*3+k] * Ki[k*3+c];
                g_Hm[(v-1)*9 + r*3 + c] = s;
            }
        for (int r = 0; r < 3; r++) {
            float s = 0;
            for (int k = 0; k < 3; k++) s += Kf[r*3+k] * tt[k];
            g_bb[(v-1)*3 + r] = s;
        }
    }
}

// ---------------- encoder ----------------
// stride-2 SAME, k=3, even input: pad_lo=0, pad_hi=1 -> in index = 2*o + k
__global__ __launch_bounds__(256) void enc1_kernel(const float* __restrict__ img,
                                                   const float* __restrict__ w,
                                                   const float* __restrict__ b) {
    __shared__ float sw[8*3*9];
    __shared__ float sb[8];
    for (int i = threadIdx.x; i < 8*3*9; i += blockDim.x) sw[i] = w[i];
    if (threadIdx.x < 8) sb[threadIdx.x] = b[threadIdx.x];
    __syncthreads();
    int idx = blockIdx.x * blockDim.x + threadIdx.x;
    if (idx >= NV*H1*W1) return;
    int x = idx % W1, y = (idx / W1) % H1, im = idx / (W1*H1);
    float acc[8];
#pragma unroll
    for (int o = 0; o < 8; o++) acc[o] = sb[o];
    const float* ib = img + im*3*HIMG*WIMG;
    for (int ic = 0; ic < 3; ic++) {
#pragma unroll
        for (int ky = 0; ky < 3; ky++) {
            int iy = 2*y + ky; if (iy >= HIMG) continue;
#pragma unroll
            for (int kx = 0; kx < 3; kx++) {
                int ix = 2*x + kx; if (ix >= WIMG) continue;
                float v = ib[(ic*HIMG + iy)*WIMG + ix];
#pragma unroll
                for (int o = 0; o < 8; o++) acc[o] += v * sw[((o*3+ic)*3+ky)*3+kx];
            }
        }
    }
#pragma unroll
    for (int o = 0; o < 8; o++)
        g_e1[((im*8+o)*H1 + y)*W1 + x] = fmaxf(acc[o], 0.0f);
}

__global__ __launch_bounds__(256) void enc2_kernel(const float* __restrict__ w,
                                                   const float* __restrict__ b) {
    __shared__ float sw[16*8*9];
    __shared__ float sb[16];
    for (int i = threadIdx.x; i < 16*8*9; i += blockDim.x) sw[i] = w[i];
    if (threadIdx.x < 16) sb[threadIdx.x] = b[threadIdx.x];
    __syncthreads();
    int idx = blockIdx.x * blockDim.x + threadIdx.x;
    if (idx >= NV*H2*W2) return;
    int x = idx % W2, y = (idx / W2) % H2, im = idx / (W2*H2);
    float acc[16];
#pragma unroll
    for (int o = 0; o < 16; o++) acc[o] = sb[o];
    const float* ib = g_e1 + im*8*H1*W1;
    for (int ic = 0; ic < 8; ic++) {
#pragma unroll
        for (int ky = 0; ky < 3; ky++) {
            int iy = 2*y + ky; if (iy >= H1) continue;
#pragma unroll
            for (int kx = 0; kx < 3; kx++) {
                int ix = 2*x + kx; if (ix >= W1) continue;
                float v = ib[(ic*H1 + iy)*W1 + ix];
#pragma unroll
                for (int o = 0; o < 16; o++) acc[o] += v * sw[((o*8+ic)*3+ky)*3+kx];
            }
        }
    }
#pragma unroll
    for (int o = 0; o < 16; o++)
        g_e2[((im*16+o)*H2 + y)*W2 + x] = fmaxf(acc[o], 0.0f);
}

__global__ __launch_bounds__(256) void enc3_kernel(const float* __restrict__ w,
                                                   const float* __restrict__ b) {
    __shared__ float sw[32*16*9];
    __shared__ float sb[32];
    for (int i = threadIdx.x; i < 32*16*9; i += blockDim.x) sw[i] = w[i];
    if (threadIdx.x < 32) sb[threadIdx.x] = b[threadIdx.x];
    __syncthreads();
    int idx = blockIdx.x * blockDim.x + threadIdx.x;
    if (idx >= NV*HFE*WFE) return;
    int x = idx % WFE, y = (idx / WFE) % HFE, im = idx / (WFE*HFE);
    float acc[32];
#pragma unroll
    for (int o = 0; o < 32; o++) acc[o] = sb[o];
    const float* ib = g_e2 + im*16*H2*W2;
    for (int ic = 0; ic < 16; ic++) {
#pragma unroll
        for (int ky = 0; ky < 3; ky++) {
            int iy = 2*y + ky; if (iy >= H2) continue;
#pragma unroll
            for (int kx = 0; kx < 3; kx++) {
                int ix = 2*x + kx; if (ix >= W2) continue;
                float v = ib[(ic*H2 + iy)*W2 + ix];
#pragma unroll
                for (int o = 0; o < 32; o++) acc[o] += v * sw[((o*16+ic)*3+ky)*3+kx];
            }
        }
    }
    // channel-last feats, no relu
#pragma unroll
    for (int o = 0; o < 32; o++)
        g_feats[((im*HFE + y)*WFE + x)*CFE + o] = acc[o];
}

// ---------------- cost volume ----------------
__global__ __launch_bounds__(256) void cost_kernel() {
    int idx = blockIdx.x * blockDim.x + threadIdx.x;
    if (idx >= ND*HFE*WFE) return;
    int x = idx % WFE, y = (idx / WFE) % HFE, d = idx / (WFE*HFE);
    float depth = g_depths[d];
    float s[CFE], ss[CFE];
    const float* f0 = g_feats + (y*WFE + x)*CFE;
#pragma unroll
    for (int c = 0; c < CFE; c++) { float v = f0[c]; s[c] = v; ss[c] = v*v; }
    float xf = (float)x, yf = (float)y;
    for (int v = 1; v < NV; v++) {
        const float* Hm = g_Hm + (v-1)*9;
        const float* bb = g_bb + (v-1)*3;
        float u  = depth*(Hm[0]*xf + Hm[1]*yf + Hm[2]) + bb[0];
        float vv = depth*(Hm[3]*xf + Hm[4]*yf + Hm[5]) + bb[1];
        float z  = depth*(Hm[6]*xf + Hm[7]*yf + Hm[8]) + bb[2];
        float valid = z > 0.001f ? 1.0f : 0.0f;
        float zc = fmaxf(z, 0.001f);
        float px = u / zc, py = vv / zc;
        float fx0 = floorf(px), fy0 = floorf(py);
        float wx = px - fx0, wy = py - fy0;
        int x0 = (int)fx0, y0 = (int)fy0;
        float w00 = (1.0f-wx)*(1.0f-wy)*valid;
        float w01 = wx*(1.0f-wy)*valid;
        float w10 = (1.0f-wx)*wy*valid;
        float w11 = wx*wy*valid;
        bool ix0 = (x0 >= 0) && (x0 < WFE);
        bool ix1 = (x0+1 >= 0) && (x0+1 < WFE);
        bool iy0 = (y0 >= 0) && (y0 < HFE);
        bool iy1 = (y0+1 >= 0) && (y0+1 < HFE);
        if (!(ix0 && iy0)) w00 = 0.0f;
        if (!(ix1 && iy0)) w01 = 0.0f;
        if (!(ix0 && iy1)) w10 = 0.0f;
        if (!(ix1 && iy1)) w11 = 0.0f;
        int cx0 = min(max(x0, 0), WFE-1), cx1 = min(max(x0+1, 0), WFE-1);
        int cy0 = min(max(y0, 0), HFE-1), cy1 = min(max(y0+1, 0), HFE-1);
        const float* base = g_feats + v*HFE*WFE*CFE;
        const float4* p00 = (const float4*)(base + (cy0*WFE + cx0)*CFE);
        const float4* p01 = (const float4*)(base + (cy0*WFE + cx1)*CFE);
        const float4* p10 = (const float4*)(base + (cy1*WFE + cx0)*CFE);
        const float4* p11 = (const float4*)(base + (cy1*WFE + cx1)*CFE);
#pragma unroll
        for (int c4 = 0; c4 < CFE/4; c4++) {
            float4 a = p00[c4], b = p01[c4], cc = p10[c4], dd = p11[c4];
            float v0 = w00*a.x + w01*b.x + w10*cc.x + w11*dd.x;
            float v1 = w00*a.y + w01*b.y + w10*cc.y + w11*dd.y;
            float v2 = w00*a.z + w01*b.z + w10*cc.z + w11*dd.z;
            float v3 = w00*a.w + w01*b.w + w10*cc.w + w11*dd.w;
            s[c4*4+0] += v0; ss[c4*4+0] += v0*v0;
            s[c4*4+1] += v1; ss[c4*4+1] += v1*v1;
            s[c4*4+2] += v2; ss[c4*4+2] += v2*v2;
            s[c4*4+3] += v3; ss[c4*4+3] += v3*v3;
        }
    }
#pragma unroll
    for (int c = 0; c < CFE; c++) {
        float mean = s[c] * 0.2f;
        g_cost[((c*ND + d)*HFE + y)*WFE + x] = ss[c]*0.2f - mean*mean;
    }
}

// ---------------- 3D conv regularization ----------------
// reg1: 32 -> 8 ch, 3x3x3, SAME, relu.  Thread = (d, y, 4 x-positions), 8 oc.
__global__ __launch_bounds__(256) void reg1_kernel(const float* __restrict__ w,
                                                   const float* __restrict__ b) {
    __shared__ float sw[8*32*27];
    __shared__ float sb[8];
    for (int i = threadIdx.x; i < 8*32*27; i += blockDim.x) sw[i] = w[i];
    if (threadIdx.x < 8) sb[threadIdx.x] = b[threadIdx.x];
    __syncthreads();
    int idx = blockIdx.x * blockDim.x + threadIdx.x;
    const int XG = WFE/4;
    if (idx >= ND*HFE*XG) return;
    int xg = idx % XG, y = (idx / XG) % HFE, d = idx / (XG*HFE);
    int xb = xg * 4;
    float acc[8][4];
#pragma unroll
    for (int o = 0; o < 8; o++) {
        float bv = sb[o];
#pragma unroll
        for (int xi = 0; xi < 4; xi++) acc[o][xi] = bv;
    }
    for (int ic = 0; ic < 32; ic++) {
#pragma unroll
        for (int kd = 0; kd < 3; kd++) {
            int dd = d + kd - 1; if (dd < 0 || dd >= ND) continue;
#pragma unroll
            for (int ky = 0; ky < 3; ky++) {
                int yy = y + ky - 1; if (yy < 0 || yy >= HFE) continue;
                const float* row = g_cost + ((ic*ND + dd)*HFE + yy)*WFE;
                float vals[6];
#pragma unroll
                for (int j = 0; j < 6; j++) {
                    int xx = xb - 1 + j;
                    vals[j] = (xx >= 0 && xx < WFE) ? row[xx] : 0.0f;
                }
#pragma unroll
                for (int kx = 0; kx < 3; kx++) {
#pragma unroll
                    for (int o = 0; o < 8; o++) {
                        float wv = sw[o*864 + ic*27 + kd*9 + ky*3 + kx];
#pragma unroll
                        for (int xi = 0; xi < 4; xi++)
                            acc[o][xi] += vals[kx + xi] * wv;
                    }
                }
            }
        }
    }
#pragma unroll
    for (int o = 0; o < 8; o++)
#pragma unroll
        for (int xi = 0; xi < 4; xi++)
            g_reg1[((o*ND + d)*HFE + y)*WFE + xb + xi] = fmaxf(acc[o][xi], 0.0f);
}

// reg2: 8 -> 1 ch, 3x3x3 SAME, no relu
__global__ __launch_bounds__(256) void reg2_kernel(const float* __restrict__ w,
                                                   const float* __restrict__ b) {
    __shared__ float sw[8*27];
    __shared__ float sb0;
    for (int i = threadIdx.x; i < 8*27; i += blockDim.x) sw[i] = w[i];
    if (threadIdx.x == 0) sb0 = b[0];
    __syncthreads();
    int idx = blockIdx.x * blockDim.x + threadIdx.x;
    if (idx >= ND*HFE*WFE) return;
    int x = idx % WFE, y = (idx / WFE) % HFE, d = idx / (WFE*HFE);
    float acc = sb0;
    for (int ic = 0; ic < 8; ic++) {
#pragma unroll
        for (int kd = 0; kd < 3; kd++) {
            int dd = d + kd - 1; if (dd < 0 || dd >= ND) continue;
#pragma unroll
            for (int ky = 0; ky < 3; ky++) {
                int yy = y + ky - 1; if (yy < 0 || yy >= HFE) continue;
#pragma unroll
                for (int kx = 0; kx < 3; kx++) {
                    int xx = x + kx - 1; if (xx < 0 || xx >= WFE) continue;
                    acc += g_reg1[((ic*ND + dd)*HFE + yy)*WFE + xx]
                         * sw[ic*27 + kd*9 + ky*3 + kx];
                }
            }
        }
    }
    g_cost2[(d*HFE + y)*WFE + x] = acc;
}

// ---------------- softmax + sum4 confidence + depth regression ----------------
// one block per pixel, 128 threads = 128 depth bins
__global__ void softmax_kernel() {
    int pix = blockIdx.x;
    int d = threadIdx.x;
    __shared__ float sred[ND];
    __shared__ float se[ND + 4];
    float c = g_cost2[d*HFE*WFE + pix];
    sred[d] = c; __syncthreads();
    for (int s = ND/2; s > 0; s >>= 1) {
        if (d < s) sred[d] = fmaxf(sred[d], sred[d+s]);
        __syncthreads();
    }
    float mx = sred[0]; __syncthreads();
    float e = expf(c - mx);
    se[d+1] = e;
    if (d == 0) { se[0] = 0.0f; se[ND+1] = 0.0f; se[ND+2] = 0.0f; se[ND+3] = 0.0f; }
    __syncthreads();
    float win = se[d] + se[d+1] + se[d+2] + se[d+3];
    // sum of e
    sred[d] = e; __syncthreads();
    for (int s = ND/2; s > 0; s >>= 1) {
        if (d < s) sred[d] += sred[d+s];
        __syncthreads();
    }
    float sume = sred[0]; __syncthreads();
    // sum of e*depth
    sred[d] = e * g_depths[d]; __syncthreads();
    for (int s = ND/2; s > 0; s >>= 1) {
        if (d < s) sred[d] += sred[d+s];
        __syncthreads();
    }
    float num = sred[0]; __syncthreads();
    // max of window sums
    sred[d] = win; __syncthreads();
    for (int s = ND/2; s > 0; s >>= 1) {
        if (d < s) sred[d] = fmaxf(sred[d], sred[d+s]);
        __syncthreads();
    }
    if (d == 0) {
        g_conf[pix] = sred[0] / sume;
        g_regd[pix] = num / sume;
    }
}

// ---------------- x8 bilinear upsample (half-pixel, clamped) ----------------
__global__ __launch_bounds__(256) void upsample_kernel(float* __restrict__ out_conf) {
    int idx = blockIdx.x * blockDim.x + threadIdx.x;
    if (idx >= HIMG*WIMG) return;
    int ox = idx % WIMG, oy = idx / WIMG;
    float fy = (oy + 0.5f) * ((float)HFE / HIMG) - 0.5f;
    float fx = (ox + 0.5f) * ((float)WFE / WIMG) - 0.5f;
    float y0f = floorf(fy), x0f = floorf(fx);
    float wy = fy - y0f, wx = fx - x0f;
    int y0 = (int)y0f, x0 = (int)x0f;
    int y0c = min(max(y0, 0), HFE-1), y1c = min(max(y0+1, 0), HFE-1);
    int x0c = min(max(x0, 0), WFE-1), x1c = min(max(x0+1, 0), WFE-1);
    float w00 = (1.0f-wx)*(1.0f-wy), w01 = wx*(1.0f-wy);
    float w10 = (1.0f-wx)*wy, w11 = wx*wy;
    float cv = w00*g_conf[y0c*WFE+x0c] + w01*g_conf[y0c*WFE+x1c]
             + w10*g_conf[y1c*WFE+x0c] + w11*g_conf[y1c*WFE+x1c];
    float rv = w00*g_regd[y0c*WFE+x0c] + w01*g_regd[y0c*WFE+x1c]
             + w10*g_regd[y1c*WFE+x0c] + w11*g_regd[y1c*WFE+x1c];
    out_conf[idx] = cv;
    g_regup[idx] = rv;
}

// ---------------- refinement ----------------
// conv1: 4 -> 32 ch, 3x3 SAME, relu.  Thread = (ocgroup of 16, y, 4 x-positions)
__global__ __launch_bounds__(256) void refine1_kernel(const float* __restrict__ img,
                                                      const float* __restrict__ w,
                                                      const float* __restrict__ b) {
    __shared__ float sw[32*4*9];
    __shared__ float sb[32];
    for (int i = threadIdx.x; i < 32*4*9; i += blockDim.x) sw[i] = w[i];
    if (threadIdx.x < 32) sb[threadIdx.x] = b[threadIdx.x];
    __syncthreads();
    int id = blockIdx.x * blockDim.x + threadIdx.x;
    const int XG = WIMG/4;
    if (id >= HIMG*XG) return;
    int ocg = blockIdx.y;                 // 0 or 1
    int xg = id % XG, y = id / XG;
    int xb = xg * 4;
    float acc[16][4];
#pragma unroll
    for (int o = 0; o < 16; o++) {
        float bv = sb[ocg*16 + o];
#pragma unroll
        for (int xi = 0; xi < 4; xi++) acc[o][xi] = bv;
    }
    for (int ic = 0; ic < 4; ic++) {
        const float* src = (ic < 3) ? (img + ic*HIMG*WIMG) : g_regup;
#pragma unroll
        for (int ky = 0; ky < 3; ky++) {
            int yy = y + ky - 1; if (yy < 0 || yy >= HIMG) continue;
            const float* row = src + yy*WIMG;
            float vals[6];
#pragma unroll
            for (int j = 0; j < 6; j++) {
                int xx = xb - 1 + j;
                vals[j] = (xx >= 0 && xx < WIMG) ? row[xx] : 0.0f;
            }
#pragma unroll
            for (int kx = 0; kx < 3; kx++) {
#pragma unroll
                for (int o = 0; o < 16; o++) {
                    float wv = sw[(((ocg*16 + o)*4 + ic)*3 + ky)*3 + kx];
#pragma unroll
                    for (int xi = 0; xi < 4; xi++)
                        acc[o][xi] += vals[kx + xi] * wv;
                }
            }
        }
    }
#pragma unroll
    for (int xi = 0; xi < 4; xi++)
#pragma unroll
        for (int o = 0; o < 16; o++)
            g_hidden[(y*WIMG + xb + xi)*32 + ocg*16 + o] = fmaxf(acc[o][xi], 0.0f);
}

// conv2: 32 -> 1 ch, 3x3 SAME; refined = regup + res
__global__ __launch_bounds__(256) void refine2_kernel(const float* __restrict__ w,
                                                      const float* __restrict__ b,
                                                      float* __restrict__ out_ref) {
    __shared__ float sw[32*9];
    __shared__ float sb0;
    for (int i = threadIdx.x; i < 32*9; i += blockDim.x) sw[i] = w[i];
    if (threadIdx.x == 0) sb0 = b[0];
    __syncthreads();
    int idx = blockIdx.x * blockDim.x + threadIdx.x;
    if (idx >= HIMG*WIMG) return;
    int x = idx % WIMG, y = idx / WIMG;
    float acc = sb0;
#pragma unroll
    for (int ky = 0; ky < 3; ky++) {
        int yy = y + ky - 1; if (yy < 0 || yy >= HIMG) continue;
#pragma unroll
        for (int kx = 0; kx < 3; kx++) {
            int xx = x + kx - 1; if (xx < 0 || xx >= WIMG) continue;
            const float4* hp = (const float4*)(g_hidden + (yy*WIMG + xx)*32);
#pragma unroll
            for (int c4 = 0; c4 < 8; c4++) {
                float4 h = hp[c4];
                acc += h.x * sw[(c4*4+0)*9 + ky*3 + kx];
                acc += h.y * sw[(c4*4+1)*9 + ky*3 + kx];
                acc += h.z * sw[(c4*4+2)*9 + ky*3 + kx];
                acc += h.w * sw[(c4*4+3)*9 + ky*3 + kx];
            }
        }
    }
    out_ref[idx] = g_regup[idx] + acc;
}

// ---------------- launch ----------------
extern "C" void kernel_launch(void* const* d_in, const int* in_sizes, int n_in,
                              void* d_out, int out_size) {
    const float* images = (const float*)d_in[0];
    const float* K      = (const float*)d_in[1];
    const float* poses  = (const float*)d_in[2];
    const float* enc_w1 = (const float*)d_in[3];
    const float* enc_b1 = (const float*)d_in[4];
    const float* enc_w2 = (const float*)d_in[5];
    const float* enc_b2 = (const float*)d_in[6];
    const float* enc_w3 = (const float*)d_in[7];
    const float* enc_b3 = (const float*)d_in[8];
    const float* reg_w1 = (const float*)d_in[9];
    const float* reg_b1 = (const float*)d_in[10];
    const float* reg_w2 = (const float*)d_in[11];
    const float* reg_b2 = (const float*)d_in[12];
    const float* ref_w1 = (const float*)d_in[13];
    const float* ref_b1 = (const float*)d_in[14];
    const float* ref_w2 = (const float*)d_in[15];
    const float* ref_b2 = (const float*)d_in[16];
    float* out = (float*)d_out;

    setup_kernel<<<1, 1>>>(K, poses);
    enc1_kernel<<<(NV*H1*W1 + 255)/256, 256>>>(images, enc_w1, enc_b1);
    enc2_kernel<<<(NV*H2*W2 + 255)/256, 256>>>(enc_w2, enc_b2);
    enc3_kernel<<<(NV*HFE*WFE + 255)/256, 256>>>(enc_w3, enc_b3);
    cost_kernel<<<(ND*HFE*WFE + 255)/256, 256>>>();
    reg1_kernel<<<(ND*HFE*(WFE/4) + 255)/256, 256>>>(reg_w1, reg_b1);
    reg2_kernel<<<(ND*HFE*WFE + 255)/256, 256>>>(reg_w2, reg_b2);
    softmax_kernel<<<HFE*WFE, ND>>>();
    upsample_kernel<<<(HIMG*WIMG + 255)/256, 256>>>(out);
    dim3 g1((HIMG*(WIMG/4) + 255)/256, 2);
    refine1_kernel<<<g1, 256>>>(images, ref_w1, ref_b1);
    refine2_kernel<<<(HIMG*WIMG + 255)/256, 256>>>(ref_w2, ref_b2, out + HIMG*WIMG);
}

// round 3
// speedup vs baseline: 1.2150x; 1.2150x over previous
#include <cuda_runtime.h>
#include <math.h>

#define NV 5
#define HIMG 512
#define WIMG 640
#define CFE 32
#define ND 128
#define HFE 64
#define WFE 80
#define H1 256
#define W1 320
#define H2 128
#define W2 160

// ---------------- scratch (device globals, no allocation) ----------------
__device__ float g_e1[NV*8*H1*W1];
__device__ float g_e2[NV*16*H2*W2];
__device__ float g_feats[NV*HFE*WFE*CFE];     // channel-last (v,y,x,c)
__device__ float g_cost[CFE*ND*HFE*WFE];      // (c,d,y,x)
__device__ float g_reg1[8*ND*HFE*WFE];        // (oc,d,y,x)
__device__ float g_cost2[ND*HFE*WFE];         // (d,y,x)
__device__ float g_conf[HFE*WFE];
__device__ float g_regd[HFE*WFE];
__device__ float g_regup[HIMG*WIMG];
__device__ float g_hidden[HIMG*WIMG*32];      // channel-last (y,x,c)
__device__ float g_Hm[4*9];
__device__ float g_bb[4*3];
__device__ float g_depths[ND];

// ---------------- f32x2 helpers ----------------
__device__ __forceinline__ unsigned long long pk2(float lo, float hi) {
    unsigned long long r;
    asm("mov.b64 %0, {%1, %2};" : "=l"(r) : "f"(lo), "f"(hi));
    return r;
}
__device__ __forceinline__ void upk2(float& lo, float& hi, unsigned long long v) {
    asm("mov.b64 {%0, %1}, %2;" : "=f"(lo), "=f"(hi) : "l"(v));
}
__device__ __forceinline__ unsigned long long fma2(unsigned long long a,
                                                   unsigned long long b,
                                                   unsigned long long c) {
    unsigned long long d;
    asm("fma.rn.f32x2 %0, %1, %2, %3;" : "=l"(d) : "l"(a), "l"(b), "l"(c));
    return d;
}

// ---------------- setup: depths + homographies ----------------
__global__ void setup_kernel(const float* __restrict__ K, const float* __restrict__ poses) {
    for (int i = 0; i < ND; i++) {
        float inv = 2.0f + (float)i * (0.2f - 2.0f) / 127.0f;
        g_depths[i] = 1.0f / inv;
    }
    float fx = K[0] / 8.0f, cx = K[2] / 8.0f, fy = K[4] / 8.0f, cy = K[5] / 8.0f;
    float Kf[9] = {fx, 0, cx, 0, fy, cy, 0, 0, 1};
    float Ki[9] = {1.0f/fx, 0, -cx/fx, 0, 1.0f/fy, -cy/fy, 0, 0, 1};
    float R0T[9], ti[3];
    for (int r = 0; r < 3; r++)
        for (int c = 0; c < 3; c++) R0T[r*3+c] = poses[c*4+r];
    for (int r = 0; r < 3; r++) {
        float s = 0;
        for (int c = 0; c < 3; c++) s += R0T[r*3+c] * poses[c*4+3];
        ti[r] = -s;
    }
    for (int v = 1; v < NV; v++) {
        const float* P = poses + v*16;
        float Rt[9], tt[3], A[9];
        for (int r = 0; r < 3; r++)
            for (int c = 0; c < 3; c++) {
                float s = 0;
                for (int k = 0; k < 3; k++) s += P[r*4+k] * R0T[k*3+c];
                Rt[r*3+c] = s;
            }
        for (int r = 0; r < 3; r++) {
            float s = 0;
            for (int k = 0; k < 3; k++) s += P[r*4+k] * ti[k];
            tt[r] = s + P[r*4+3];
        }
        for (int r = 0; r < 3; r++)
            for (int c = 0; c < 3; c++) {
                float s = 0;
                for (int k = 0; k < 3; k++) s += Kf[r*3+k] * Rt[k*3+c];
                A[r*3+c] = s;
            }
        for (int r = 0; r < 3; r++)
            for (int c = 0; c < 3; c++) {
                float s = 0;
                for (int k = 0; k < 3; k++) s += A[r*3+k] * Ki[k*3+c];
                g_Hm[(v-1)*9 + r*3 + c] = s;
            }
        for (int r = 0; r < 3; r++) {
            float s = 0;
            for (int k = 0; k < 3; k++) s += Kf[r*3+k] * tt[k];
            g_bb[(v-1)*3 + r] = s;
        }
    }
}

// ---------------- encoder ----------------
__global__ __launch_bounds__(256) void enc1_kernel(const float* __restrict__ img,
                                                   const float* __restrict__ w,
                                                   const float* __restrict__ b) {
    __shared__ float sw[8*3*9];
    __shared__ float sb[8];
    for (int i = threadIdx.x; i < 8*3*9; i += blockDim.x) sw[i] = w[i];
    if (threadIdx.x < 8) sb[threadIdx.x] = b[threadIdx.x];
    __syncthreads();
    int idx = blockIdx.x * blockDim.x + threadIdx.x;
    if (idx >= NV*H1*W1) return;
    int x = idx % W1, y = (idx / W1) % H1, im = idx / (W1*H1);
    float acc[8];
#pragma unroll
    for (int o = 0; o < 8; o++) acc[o] = sb[o];
    const float* ib = img + im*3*HIMG*WIMG;
    for (int ic = 0; ic < 3; ic++) {
#pragma unroll
        for (int ky = 0; ky < 3; ky++) {
            int iy = 2*y + ky; if (iy >= HIMG) continue;
#pragma unroll
            for (int kx = 0; kx < 3; kx++) {
                int ix = 2*x + kx; if (ix >= WIMG) continue;
                float v = ib[(ic*HIMG + iy)*WIMG + ix];
#pragma unroll
                for (int o = 0; o < 8; o++) acc[o] += v * sw[((o*3+ic)*3+ky)*3+kx];
            }
        }
    }
#pragma unroll
    for (int o = 0; o < 8; o++)
        g_e1[((im*8+o)*H1 + y)*W1 + x] = fmaxf(acc[o], 0.0f);
}

__global__ __launch_bounds__(256) void enc2_kernel(const float* __restrict__ w,
                                                   const float* __restrict__ b) {
    __shared__ float sw[16*8*9];
    __shared__ float sb[16];
    for (int i = threadIdx.x; i < 16*8*9; i += blockDim.x) sw[i] = w[i];
    if (threadIdx.x < 16) sb[threadIdx.x] = b[threadIdx.x];
    __syncthreads();
    int idx = blockIdx.x * blockDim.x + threadIdx.x;
    if (idx >= NV*H2*W2) return;
    int x = idx % W2, y = (idx / W2) % H2, im = idx / (W2*H2);
    float acc[16];
#pragma unroll
    for (int o = 0; o < 16; o++) acc[o] = sb[o];
    const float* ib = g_e1 + im*8*H1*W1;
    for (int ic = 0; ic < 8; ic++) {
#pragma unroll
        for (int ky = 0; ky < 3; ky++) {
            int iy = 2*y + ky; if (iy >= H1) continue;
#pragma unroll
            for (int kx = 0; kx < 3; kx++) {
                int ix = 2*x + kx; if (ix >= W1) continue;
                float v = ib[(ic*H1 + iy)*W1 + ix];
#pragma unroll
                for (int o = 0; o < 16; o++) acc[o] += v * sw[((o*8+ic)*3+ky)*3+kx];
            }
        }
    }
#pragma unroll
    for (int o = 0; o < 16; o++)
        g_e2[((im*16+o)*H2 + y)*W2 + x] = fmaxf(acc[o], 0.0f);
}

// enc3: 16 -> 32 ch, stride 2; thread = (im, y, 4 x-positions), oc group of 8 via grid.y
__global__ __launch_bounds__(128) void enc3_kernel(const float* __restrict__ w,
                                                   const float* __restrict__ b) {
    __shared__ float sw[8*16*9];
    __shared__ float sb[8];
    int ocg = blockIdx.y;  // 0..3
    for (int i = threadIdx.x; i < 8*16*9; i += blockDim.x) {
        int o = i / 144, rest = i % 144;
        sw[i] = w[(ocg*8 + o)*144 + rest];
    }
    if (threadIdx.x < 8) sb[threadIdx.x] = b[ocg*8 + threadIdx.x];
    __syncthreads();
    int idx = blockIdx.x * blockDim.x + threadIdx.x;
    const int XG = WFE/4;  // 20
    if (idx >= NV*HFE*XG) return;
    int xg = idx % XG, y = (idx / XG) % HFE, im = idx / (XG*HFE);
    int xb = xg * 4;
    float acc[8][4];
#pragma unroll
    for (int o = 0; o < 8; o++) {
        float bv = sb[o];
#pragma unroll
        for (int xi = 0; xi < 4; xi++) acc[o][xi] = bv;
    }
    const float* ib = g_e2 + im*16*H2*W2;
    for (int ic = 0; ic < 16; ic++) {
#pragma unroll
        for (int ky = 0; ky < 3; ky++) {
            int iy = 2*y + ky; if (iy >= H2) continue;
            const float* row = ib + (ic*H2 + iy)*W2 + 2*xb;
            float v[9];
            float4 q0 = *(const float4*)row;
            float4 q1 = *(const float4*)(row + 4);
            v[0]=q0.x; v[1]=q0.y; v[2]=q0.z; v[3]=q0.w;
            v[4]=q1.x; v[5]=q1.y; v[6]=q1.z; v[7]=q1.w;
            v[8] = (2*xb + 8 < W2) ? row[8] : 0.0f;
#pragma unroll
            for (int kx = 0; kx < 3; kx++) {
#pragma unroll
                for (int o = 0; o < 8; o++) {
                    float wv = sw[(o*16+ic)*9 + ky*3 + kx];
#pragma unroll
                    for (int xi = 0; xi < 4; xi++)
                        acc[o][xi] += v[2*xi + kx] * wv;
                }
            }
        }
    }
#pragma unroll
    for (int xi = 0; xi < 4; xi++)
#pragma unroll
        for (int o = 0; o < 8; o++)
            g_feats[((im*HFE + y)*WFE + xb + xi)*CFE + ocg*8 + o] = acc[o][xi];
}

// ---------------- cost volume ----------------
__global__ __launch_bounds__(256) void cost_kernel() {
    int idx = blockIdx.x * blockDim.x + threadIdx.x;
    if (idx >= ND*HFE*WFE) return;
    int x = idx % WFE, y = (idx / WFE) % HFE, d = idx / (WFE*HFE);
    float depth = g_depths[d];
    float s[CFE], ss[CFE];
    const float* f0 = g_feats + (y*WFE + x)*CFE;
#pragma unroll
    for (int c = 0; c < CFE; c++) { float v = f0[c]; s[c] = v; ss[c] = v*v; }
    float xf = (float)x, yf = (float)y;
    for (int v = 1; v < NV; v++) {
        const float* Hm = g_Hm + (v-1)*9;
        const float* bb = g_bb + (v-1)*3;
        float u  = depth*(Hm[0]*xf + Hm[1]*yf + Hm[2]) + bb[0];
        float vv = depth*(Hm[3]*xf + Hm[4]*yf + Hm[5]) + bb[1];
        float z  = depth*(Hm[6]*xf + Hm[7]*yf + Hm[8]) + bb[2];
        float valid = z > 0.001f ? 1.0f : 0.0f;
        float zc = fmaxf(z, 0.001f);
        float px = u / zc, py = vv / zc;
        float fx0 = floorf(px), fy0 = floorf(py);
        float wx = px - fx0, wy = py - fy0;
        int x0 = (int)fx0, y0 = (int)fy0;
        float w00 = (1.0f-wx)*(1.0f-wy)*valid;
        float w01 = wx*(1.0f-wy)*valid;
        float w10 = (1.0f-wx)*wy*valid;
        float w11 = wx*wy*valid;
        bool ix0 = (x0 >= 0) && (x0 < WFE);
        bool ix1 = (x0+1 >= 0) && (x0+1 < WFE);
        bool iy0 = (y0 >= 0) && (y0 < HFE);
        bool iy1 = (y0+1 >= 0) && (y0+1 < HFE);
        if (!(ix0 && iy0)) w00 = 0.0f;
        if (!(ix1 && iy0)) w01 = 0.0f;
        if (!(ix0 && iy1)) w10 = 0.0f;
        if (!(ix1 && iy1)) w11 = 0.0f;
        int cx0 = min(max(x0, 0), WFE-1), cx1 = min(max(x0+1, 0), WFE-1);
        int cy0 = min(max(y0, 0), HFE-1), cy1 = min(max(y0+1, 0), HFE-1);
        const float* base = g_feats + v*HFE*WFE*CFE;
        const float4* p00 = (const float4*)(base + (cy0*WFE + cx0)*CFE);
        const float4* p01 = (const float4*)(base + (cy0*WFE + cx1)*CFE);
        const float4* p10 = (const float4*)(base + (cy1*WFE + cx0)*CFE);
        const float4* p11 = (const float4*)(base + (cy1*WFE + cx1)*CFE);
#pragma unroll
        for (int c4 = 0; c4 < CFE/4; c4++) {
            float4 a = p00[c4], b = p01[c4], cc = p10[c4], dd = p11[c4];
            float v0 = w00*a.x + w01*b.x + w10*cc.x + w11*dd.x;
            float v1 = w00*a.y + w01*b.y + w10*cc.y + w11*dd.y;
            float v2 = w00*a.z + w01*b.z + w10*cc.z + w11*dd.z;
            float v3 = w00*a.w + w01*b.w + w10*cc.w + w11*dd.w;
            s[c4*4+0] += v0; ss[c4*4+0] += v0*v0;
            s[c4*4+1] += v1; ss[c4*4+1] += v1*v1;
            s[c4*4+2] += v2; ss[c4*4+2] += v2*v2;
            s[c4*4+3] += v3; ss[c4*4+3] += v3*v3;
        }
    }
#pragma unroll
    for (int c = 0; c < CFE; c++) {
        float mean = s[c] * 0.2f;
        g_cost[((c*ND + d)*HFE + y)*WFE + x] = ss[c]*0.2f - mean*mean;
    }
}

// ---------------- reg1: smem-tiled, f32x2 ----------------
// tile: D_T=4, Y_T=2, full x row (80). 160 threads = 20 xg * 2 ty * 4 td.
// smem: weights for 8-ic chunk (864 ull) + input chunk 8ic x 6dd x 4yy x 84 floats.
#define R1_SW_ULL 864
#define R1_XSTR 84
#define R1_IN_FLOATS (8*6*4*R1_XSTR)
#define R1_SMEM_BYTES (R1_SW_ULL*8 + R1_IN_FLOATS*4)

__global__ __launch_bounds__(160) void reg1_kernel(const float* __restrict__ w,
                                                   const float* __restrict__ b) {
    extern __shared__ char smem_raw[];
    unsigned long long* s_w = (unsigned long long*)smem_raw;
    float* s_in = (float*)(smem_raw + R1_SW_ULL*8);

    int tid = threadIdx.x;
    int xg = tid % 20;
    int ty = (tid / 20) % 2;
    int td = tid / 40;
    int xb = xg * 4;

    int bx = blockIdx.x;
    int y0 = (bx % (HFE/2)) * 2;
    int d0 = (bx / (HFE/2)) * 4;
    int d = d0 + td, y = y0 + ty;

    unsigned long long acc2[4][4];
#pragma unroll
    for (int op = 0; op < 4; op++) {
        unsigned long long bv = pk2(b[2*op], b[2*op+1]);
#pragma unroll
        for (int xi = 0; xi < 4; xi++) acc2[op][xi] = bv;
    }

#pragma unroll 1
    for (int ch = 0; ch < 4; ch++) {
        // load weights for this ic chunk: s_w[(icl*27 + k)*4 + op] = (w[2op], w[2op+1])
        for (int e = tid; e < R1_SW_ULL; e += 160) {
            int icl = e / 108, rem = e % 108;
            int k = rem >> 2, op = rem & 3;
            int ic = ch*8 + icl;
            float lo = w[(2*op)*864 + ic*27 + k];
            float hi = w[(2*op+1)*864 + ic*27 + k];
            s_w[e] = pk2(lo, hi);
        }
        // load input chunk rows (192 rows of 80 + zero halo in x)
        for (int r = tid; r < 192; r += 160) {
            int icl = r / 24, rem = r % 24;
            int ddl = rem / 4, yyl = rem % 4;
            int dd = d0 - 1 + ddl, yy = y0 - 1 + yyl;
            bool inr = (dd >= 0) && (dd < ND) && (yy >= 0) && (yy < HFE);
            float* srow = s_in + ((icl*6 + ddl)*4 + yyl)*R1_XSTR;
            const float* grow = g_cost + (((ch*8 + icl)*ND + dd)*HFE + yy)*WFE;
            srow[0] = 0.0f; srow[81] = 0.0f;
            if (inr) {
#pragma unroll
                for (int xq = 0; xq < 20; xq++) {
                    float4 v = *(const float4*)(grow + 4*xq);
                    srow[1+4*xq+0] = v.x; srow[1+4*xq+1] = v.y;
                    srow[1+4*xq+2] = v.z; srow[1+4*xq+3] = v.w;
                }
            } else {
#pragma unroll
                for (int xq = 0; xq < 20; xq++) {
                    srow[1+4*xq+0] = 0.0f; srow[1+4*xq+1] = 0.0f;
                    srow[1+4*xq+2] = 0.0f; srow[1+4*xq+3] = 0.0f;
                }
            }
        }
        __syncthreads();

#pragma unroll 1
        for (int icl = 0; icl < 8; icl++) {
#pragma unroll
            for (int kd = 0; kd < 3; kd++) {
#pragma unroll
                for (int ky = 0; ky < 3; ky++) {
                    const float* srow = s_in + ((icl*6 + td + kd)*4 + ty + ky)*R1_XSTR + xb;
                    unsigned long long v2[6];
#pragma unroll
                    for (int i = 0; i < 6; i++) {
                        float v = srow[i];
                        v2[i] = pk2(v, v);
                    }
                    const unsigned long long* wrow = s_w + (icl*27 + kd*9 + ky*3)*4;
#pragma unroll
                    for (int kx = 0; kx < 3; kx++) {
#pragma unroll
                        for (int op = 0; op < 4; op++) {
                            unsigned long long w2 = wrow[kx*4 + op];
#pragma unroll
                            for (int xi = 0; xi < 4; xi++)
                                acc2[op][xi] = fma2(v2[xi + kx], w2, acc2[op][xi]);
                        }
                    }
                }
            }
        }
        __syncthreads();
    }

#pragma unroll
    for (int op = 0; op < 4; op++)
#pragma unroll
        for (int xi = 0; xi < 4; xi++) {
            float lo, hi;
            upk2(lo, hi, acc2[op][xi]);
            g_reg1[(((2*op)*ND + d)*HFE + y)*WFE + xb + xi]   = fmaxf(lo, 0.0f);
            g_reg1[(((2*op+1)*ND + d)*HFE + y)*WFE + xb + xi] = fmaxf(hi, 0.0f);
        }
}

// reg2: 8 -> 1 ch, 3x3x3 SAME; thread = (d, y, 4 x)
__global__ __launch_bounds__(256) void reg2_kernel(const float* __restrict__ w,
                                                   const float* __restrict__ b) {
    __shared__ float sw[8*27];
    __shared__ float sb0;
    for (int i = threadIdx.x; i < 8*27; i += blockDim.x) sw[i] = w[i];
    if (threadIdx.x == 0) sb0 = b[0];
    __syncthreads();
    int idx = blockIdx.x * blockDim.x + threadIdx.x;
    const int XG = WFE/4;
    if (idx >= ND*HFE*XG) return;
    int xg = idx % XG, y = (idx / XG) % HFE, d = idx / (XG*HFE);
    int xb = xg * 4;
    float acc[4];
#pragma unroll
    for (int xi = 0; xi < 4; xi++) acc[xi] = sb0;
    for (int ic = 0; ic < 8; ic++) {
#pragma unroll
        for (int kd = 0; kd < 3; kd++) {
            int dd = d + kd - 1; if (dd < 0 || dd >= ND) continue;
#pragma unroll
            for (int ky = 0; ky < 3; ky++) {
                int yy = y + ky - 1; if (yy < 0 || yy >= HFE) continue;
                const float* row = g_reg1 + ((ic*ND + dd)*HFE + yy)*WFE;
                float vals[6];
#pragma unroll
                for (int j = 0; j < 6; j++) {
                    int xx = xb - 1 + j;
                    vals[j] = (xx >= 0 && xx < WFE) ? row[xx] : 0.0f;
                }
#pragma unroll
                for (int kx = 0; kx < 3; kx++) {
                    float wv = sw[ic*27 + kd*9 + ky*3 + kx];
#pragma unroll
                    for (int xi = 0; xi < 4; xi++)
                        acc[xi] += vals[kx + xi] * wv;
                }
            }
        }
    }
#pragma unroll
    for (int xi = 0; xi < 4; xi++)
        g_cost2[(d*HFE + y)*WFE + xb + xi] = acc[xi];
}

// ---------------- softmax + sum4 confidence + depth regression ----------------
__global__ void softmax_kernel() {
    int pix = blockIdx.x;
    int d = threadIdx.x;
    __shared__ float sred[ND];
    __shared__ float se[ND + 4];
    float c = g_cost2[d*HFE*WFE + pix];
    sred[d] = c; __syncthreads();
    for (int s = ND/2; s > 0; s >>= 1) {
        if (d < s) sred[d] = fmaxf(sred[d], sred[d+s]);
        __syncthreads();
    }
    float mx = sred[0]; __syncthreads();
    float e = expf(c - mx);
    se[d+1] = e;
    if (d == 0) { se[0] = 0.0f; se[ND+1] = 0.0f; se[ND+2] = 0.0f; se[ND+3] = 0.0f; }
    __syncthreads();
    float win = se[d] + se[d+1] + se[d+2] + se[d+3];
    sred[d] = e; __syncthreads();
    for (int s = ND/2; s > 0; s >>= 1) {
        if (d < s) sred[d] += sred[d+s];
        __syncthreads();
    }
    float sume = sred[0]; __syncthreads();
    sred[d] = e * g_depths[d]; __syncthreads();
    for (int s = ND/2; s > 0; s >>= 1) {
        if (d < s) sred[d] += sred[d+s];
        __syncthreads();
    }
    float num = sred[0]; __syncthreads();
    sred[d] = win; __syncthreads();
    for (int s = ND/2; s > 0; s >>= 1) {
        if (d < s) sred[d] = fmaxf(sred[d], sred[d+s]);
        __syncthreads();
    }
    if (d == 0) {
        g_conf[pix] = sred[0] / sume;
        g_regd[pix] = num / sume;
    }
}

// ---------------- x8 bilinear upsample ----------------
__global__ __launch_bounds__(256) void upsample_kernel(float* __restrict__ out_conf) {
    int idx = blockIdx.x * blockDim.x + threadIdx.x;
    if (idx >= HIMG*WIMG) return;
    int ox = idx % WIMG, oy = idx / WIMG;
    float fy = (oy + 0.5f) * ((float)HFE / HIMG) - 0.5f;
    float fx = (ox + 0.5f) * ((float)WFE / WIMG) - 0.5f;
    float y0f = floorf(fy), x0f = floorf(fx);
    float wy = fy - y0f, wx = fx - x0f;
    int y0 = (int)y0f, x0 = (int)x0f;
    int y0c = min(max(y0, 0), HFE-1), y1c = min(max(y0+1, 0), HFE-1);
    int x0c = min(max(x0, 0), WFE-1), x1c = min(max(x0+1, 0), WFE-1);
    float w00 = (1.0f-wx)*(1.0f-wy), w01 = wx*(1.0f-wy);
    float w10 = (1.0f-wx)*wy, w11 = wx*wy;
    float cv = w00*g_conf[y0c*WFE+x0c] + w01*g_conf[y0c*WFE+x1c]
             + w10*g_conf[y1c*WFE+x0c] + w11*g_conf[y1c*WFE+x1c];
    float rv = w00*g_regd[y0c*WFE+x0c] + w01*g_regd[y0c*WFE+x1c]
             + w10*g_regd[y1c*WFE+x0c] + w11*g_regd[y1c*WFE+x1c];
    out_conf[idx] = cv;
    g_regup[idx] = rv;
}

// ---------------- refinement ----------------
__global__ __launch_bounds__(256) void refine1_kernel(const float* __restrict__ img,
                                                      const float* __restrict__ w,
                                                      const float* __restrict__ b) {
    __shared__ float sw[32*4*9];
    __shared__ float sb[32];
    for (int i = threadIdx.x; i < 32*4*9; i += blockDim.x) sw[i] = w[i];
    if (threadIdx.x < 32) sb[threadIdx.x] = b[threadIdx.x];
    __syncthreads();
    int id = blockIdx.x * blockDim.x + threadIdx.x;
    const int XG = WIMG/4;
    if (id >= HIMG*XG) return;
    int ocg = blockIdx.y;
    int xg = id % XG, y = id / XG;
    int xb = xg * 4;
    float acc[16][4];
#pragma unroll
    for (int o = 0; o < 16; o++) {
        float bv = sb[ocg*16 + o];
#pragma unroll
        for (int xi = 0; xi < 4; xi++) acc[o][xi] = bv;
    }
    for (int ic = 0; ic < 4; ic++) {
        const float* src = (ic < 3) ? (img + ic*HIMG*WIMG) : g_regup;
#pragma unroll
        for (int ky = 0; ky < 3; ky++) {
            int yy = y + ky - 1; if (yy < 0 || yy >= HIMG) continue;
            const float* row = src + yy*WIMG;
            float vals[6];
#pragma unroll
            for (int j = 0; j < 6; j++) {
                int xx = xb - 1 + j;
                vals[j] = (xx >= 0 && xx < WIMG) ? row[xx] : 0.0f;
            }
#pragma unroll
            for (int kx = 0; kx < 3; kx++) {
#pragma unroll
                for (int o = 0; o < 16; o++) {
                    float wv = sw[(((ocg*16 + o)*4 + ic)*3 + ky)*3 + kx];
#pragma unroll
                    for (int xi = 0; xi < 4; xi++)
                        acc[o][xi] += vals[kx + xi] * wv;
                }
            }
        }
    }
#pragma unroll
    for (int xi = 0; xi < 4; xi++)
#pragma unroll
        for (int o = 0; o < 16; o++)
            g_hidden[(y*WIMG + xb + xi)*32 + ocg*16 + o] = fmaxf(acc[o][xi], 0.0f);
}

__global__ __launch_bounds__(256) void refine2_kernel(const float* __restrict__ w,
                                                      const float* __restrict__ b,
                                                      float* __restrict__ out_ref) {
    __shared__ float sw[32*9];
    __shared__ float sb0;
    for (int i = threadIdx.x; i < 32*9; i += blockDim.x) sw[i] = w[i];
    if (threadIdx.x == 0) sb0 = b[0];
    __syncthreads();
    int idx = blockIdx.x * blockDim.x + threadIdx.x;
    if (idx >= HIMG*WIMG) return;
    int x = idx % WIMG, y = idx / WIMG;
    float acc = sb0;
#pragma unroll
    for (int ky = 0; ky < 3; ky++) {
        int yy = y + ky - 1; if (yy < 0 || yy >= HIMG) continue;
#pragma unroll
        for (int kx = 0; kx < 3; kx++) {
            int xx = x + kx - 1; if (xx < 0 || xx >= WIMG) continue;
            const float4* hp = (const float4*)(g_hidden + (yy*WIMG + xx)*32);
#pragma unroll
            for (int c4 = 0; c4 < 8; c4++) {
                float4 h = hp[c4];
                acc += h.x * sw[(c4*4+0)*9 + ky*3 + kx];
                acc += h.y * sw[(c4*4+1)*9 + ky*3 + kx];
                acc += h.z * sw[(c4*4+2)*9 + ky*3 + kx];
                acc += h.w * sw[(c4*4+3)*9 + ky*3 + kx];
            }
        }
    }
    out_ref[idx] = g_regup[idx] + acc;
}

// ---------------- launch ----------------
extern "C" void kernel_launch(void* const* d_in, const int* in_sizes, int n_in,
                              void* d_out, int out_size) {
    const float* images = (const float*)d_in[0];
    const float* K      = (const float*)d_in[1];
    const float* poses  = (const float*)d_in[2];
    const float* enc_w1 = (const float*)d_in[3];
    const float* enc_b1 = (const float*)d_in[4];
    const float* enc_w2 = (const float*)d_in[5];
    const float* enc_b2 = (const float*)d_in[6];
    const float* enc_w3 = (const float*)d_in[7];
    const float* enc_b3 = (const float*)d_in[8];
    const float* reg_w1 = (const float*)d_in[9];
    const float* reg_b1 = (const float*)d_in[10];
    const float* reg_w2 = (const float*)d_in[11];
    const float* reg_b2 = (const float*)d_in[12];
    const float* ref_w1 = (const float*)d_in[13];
    const float* ref_b1 = (const float*)d_in[14];
    const float* ref_w2 = (const float*)d_in[15];
    const float* ref_b2 = (const float*)d_in[16];
    float* out = (float*)d_out;

    static bool attr_set = false;
    if (!attr_set) {
        cudaFuncSetAttribute(reg1_kernel, cudaFuncAttributeMaxDynamicSharedMemorySize,
                             R1_SMEM_BYTES);
        attr_set = true;
    }

    setup_kernel<<<1, 1>>>(K, poses);
    enc1_kernel<<<(NV*H1*W1 + 255)/256, 256>>>(images, enc_w1, enc_b1);
    enc2_kernel<<<(NV*H2*W2 + 255)/256, 256>>>(enc_w2, enc_b2);
    dim3 g3((NV*HFE*(WFE/4) + 127)/128, 4);
    enc3_kernel<<<g3, 128>>>(enc_w3, enc_b3);
    cost_kernel<<<(ND*HFE*WFE + 255)/256, 256>>>();
    reg1_kernel<<<(HFE/2)*(ND/4), 160, R1_SMEM_BYTES>>>(reg_w1, reg_b1);
    reg2_kernel<<<(ND*HFE*(WFE/4) + 255)/256, 256>>>(reg_w2, reg_b2);
    softmax_kernel<<<HFE*WFE, ND>>>();
    upsample_kernel<<<(HIMG*WIMG + 255)/256, 256>>>(out);
    dim3 g1((HIMG*(WIMG/4) + 255)/256, 2);
    refine1_kernel<<<g1, 256>>>(images, ref_w1, ref_b1);
    refine2_kernel<<<(HIMG*WIMG + 255)/256, 256>>>(ref_w2, ref_b2, out + HIMG*WIMG);
}

// round 4
// speedup vs baseline: 1.6997x; 1.3989x over previous
#include <cuda_runtime.h>
#include <math.h>

#define NV 5
#define HIMG 512
#define WIMG 640
#define CFE 32
#define ND 128
#define HFE 64
#define WFE 80
#define H1 256
#define W1 320
#define H2 128
#define W2 160
#define HWF (HFE*WFE)
#define HWI (HIMG*WIMG)

// ---------------- scratch (device globals, no allocation) ----------------
__device__ float g_e1[NV*8*H1*W1];
__device__ float g_e2[NV*16*H2*W2];
__device__ float4 g_feats4[NV*8*HWF];         // plane-major: [v][c4][y*x] float4
__device__ float g_cost[CFE*ND*HWF];          // (c,d,y,x)
__device__ float g_reg1[8*ND*HWF];            // (oc,d,y,x)
__device__ float g_cost2[ND*HWF];             // (d,y,x)
__device__ float g_conf[HWF];
__device__ float g_regd[HWF];
__device__ float g_regup[HWI];
__device__ float4 g_hidden4[8*HWI];           // plane-major: [c4][y*x] float4
__device__ float g_Hm[4*9];
__device__ float g_bb[4*3];
__device__ float g_depths[ND];

// ---------------- f32x2 helpers ----------------
__device__ __forceinline__ unsigned long long pk2(float lo, float hi) {
    unsigned long long r;
    asm("mov.b64 %0, {%1, %2};" : "=l"(r) : "f"(lo), "f"(hi));
    return r;
}
__device__ __forceinline__ void upk2(float& lo, float& hi, unsigned long long v) {
    asm("mov.b64 {%0, %1}, %2;" : "=f"(lo), "=f"(hi) : "l"(v));
}
__device__ __forceinline__ unsigned long long fma2(unsigned long long a,
                                                   unsigned long long b,
                                                   unsigned long long c) {
    unsigned long long d;
    asm("fma.rn.f32x2 %0, %1, %2, %3;" : "=l"(d) : "l"(a), "l"(b), "l"(c));
    return d;
}

// ---------------- setup: depths + homographies ----------------
__global__ void setup_kernel(const float* __restrict__ K, const float* __restrict__ poses) {
    for (int i = 0; i < ND; i++) {
        float inv = 2.0f + (float)i * (0.2f - 2.0f) / 127.0f;
        g_depths[i] = 1.0f / inv;
    }
    float fx = K[0] / 8.0f, cx = K[2] / 8.0f, fy = K[4] / 8.0f, cy = K[5] / 8.0f;
    float Kf[9] = {fx, 0, cx, 0, fy, cy, 0, 0, 1};
    float Ki[9] = {1.0f/fx, 0, -cx/fx, 0, 1.0f/fy, -cy/fy, 0, 0, 1};
    float R0T[9], ti[3];
    for (int r = 0; r < 3; r++)
        for (int c = 0; c < 3; c++) R0T[r*3+c] = poses[c*4+r];
    for (int r = 0; r < 3; r++) {
        float s = 0;
        for (int c = 0; c < 3; c++) s += R0T[r*3+c] * poses[c*4+3];
        ti[r] = -s;
    }
    for (int v = 1; v < NV; v++) {
        const float* P = poses + v*16;
        float Rt[9], tt[3], A[9];
        for (int r = 0; r < 3; r++)
            for (int c = 0; c < 3; c++) {
                float s = 0;
                for (int k = 0; k < 3; k++) s += P[r*4+k] * R0T[k*3+c];
                Rt[r*3+c] = s;
            }
        for (int r = 0; r < 3; r++) {
            float s = 0;
            for (int k = 0; k < 3; k++) s += P[r*4+k] * ti[k];
            tt[r] = s + P[r*4+3];
        }
        for (int r = 0; r < 3; r++)
            for (int c = 0; c < 3; c++) {
                float s = 0;
                for (int k = 0; k < 3; k++) s += Kf[r*3+k] * Rt[k*3+c];
                A[r*3+c] = s;
            }
        for (int r = 0; r < 3; r++)
            for (int c = 0; c < 3; c++) {
                float s = 0;
                for (int k = 0; k < 3; k++) s += A[r*3+k] * Ki[k*3+c];
                g_Hm[(v-1)*9 + r*3 + c] = s;
            }
        for (int r = 0; r < 3; r++) {
            float s = 0;
            for (int k = 0; k < 3; k++) s += Kf[r*3+k] * tt[k];
            g_bb[(v-1)*3 + r] = s;
        }
    }
}

// ---------------- encoder ----------------
__global__ __launch_bounds__(256) void enc1_kernel(const float* __restrict__ img,
                                                   const float* __restrict__ w,
                                                   const float* __restrict__ b) {
    __shared__ float sw[8*3*9];
    __shared__ float sb[8];
    for (int i = threadIdx.x; i < 8*3*9; i += blockDim.x) sw[i] = w[i];
    if (threadIdx.x < 8) sb[threadIdx.x] = b[threadIdx.x];
    __syncthreads();
    int idx = blockIdx.x * blockDim.x + threadIdx.x;
    if (idx >= NV*H1*W1) return;
    int x = idx % W1, y = (idx / W1) % H1, im = idx / (W1*H1);
    float acc[8];
#pragma unroll
    for (int o = 0; o < 8; o++) acc[o] = sb[o];
    const float* ib = img + im*3*HIMG*WIMG;
    for (int ic = 0; ic < 3; ic++) {
#pragma unroll
        for (int ky = 0; ky < 3; ky++) {
            int iy = 2*y + ky; if (iy >= HIMG) continue;
#pragma unroll
            for (int kx = 0; kx < 3; kx++) {
                int ix = 2*x + kx; if (ix >= WIMG) continue;
                float v = ib[(ic*HIMG + iy)*WIMG + ix];
#pragma unroll
                for (int o = 0; o < 8; o++) acc[o] += v * sw[((o*3+ic)*3+ky)*3+kx];
            }
        }
    }
#pragma unroll
    for (int o = 0; o < 8; o++)
        g_e1[((im*8+o)*H1 + y)*W1 + x] = fmaxf(acc[o], 0.0f);
}

__global__ __launch_bounds__(256) void enc2_kernel(const float* __restrict__ w,
                                                   const float* __restrict__ b) {
    __shared__ float sw[16*8*9];
    __shared__ float sb[16];
    for (int i = threadIdx.x; i < 16*8*9; i += blockDim.x) sw[i] = w[i];
    if (threadIdx.x < 16) sb[threadIdx.x] = b[threadIdx.x];
    __syncthreads();
    int idx = blockIdx.x * blockDim.x + threadIdx.x;
    if (idx >= NV*H2*W2) return;
    int x = idx % W2, y = (idx / W2) % H2, im = idx / (W2*H2);
    float acc[16];
#pragma unroll
    for (int o = 0; o < 16; o++) acc[o] = sb[o];
    const float* ib = g_e1 + im*8*H1*W1;
    for (int ic = 0; ic < 8; ic++) {
#pragma unroll
        for (int ky = 0; ky < 3; ky++) {
            int iy = 2*y + ky; if (iy >= H1) continue;
#pragma unroll
            for (int kx = 0; kx < 3; kx++) {
                int ix = 2*x + kx; if (ix >= W1) continue;
                float v = ib[(ic*H1 + iy)*W1 + ix];
#pragma unroll
                for (int o = 0; o < 16; o++) acc[o] += v * sw[((o*8+ic)*3+ky)*3+kx];
            }
        }
    }
#pragma unroll
    for (int o = 0; o < 16; o++)
        g_e2[((im*16+o)*H2 + y)*W2 + x] = fmaxf(acc[o], 0.0f);
}

// enc3: 16 -> 32 ch, stride 2; thread = (im, y, 4 x-positions), oc group of 8 via grid.y
__global__ __launch_bounds__(128) void enc3_kernel(const float* __restrict__ w,
                                                   const float* __restrict__ b) {
    __shared__ float sw[8*16*9];
    __shared__ float sb[8];
    int ocg = blockIdx.y;  // 0..3
    for (int i = threadIdx.x; i < 8*16*9; i += blockDim.x) {
        int o = i / 144, rest = i % 144;
        sw[i] = w[(ocg*8 + o)*144 + rest];
    }
    if (threadIdx.x < 8) sb[threadIdx.x] = b[ocg*8 + threadIdx.x];
    __syncthreads();
    int idx = blockIdx.x * blockDim.x + threadIdx.x;
    const int XG = WFE/4;  // 20
    if (idx >= NV*HFE*XG) return;
    int xg = idx % XG, y = (idx / XG) % HFE, im = idx / (XG*HFE);
    int xb = xg * 4;
    float acc[8][4];
#pragma unroll
    for (int o = 0; o < 8; o++) {
        float bv = sb[o];
#pragma unroll
        for (int xi = 0; xi < 4; xi++) acc[o][xi] = bv;
    }
    const float* ib = g_e2 + im*16*H2*W2;
    for (int ic = 0; ic < 16; ic++) {
#pragma unroll
        for (int ky = 0; ky < 3; ky++) {
            int iy = 2*y + ky; if (iy >= H2) continue;
            const float* row = ib + (ic*H2 + iy)*W2 + 2*xb;
            float v[9];
            float4 q0 = *(const float4*)row;
            float4 q1 = *(const float4*)(row + 4);
            v[0]=q0.x; v[1]=q0.y; v[2]=q0.z; v[3]=q0.w;
            v[4]=q1.x; v[5]=q1.y; v[6]=q1.z; v[7]=q1.w;
            v[8] = (2*xb + 8 < W2) ? row[8] : 0.0f;
#pragma unroll
            for (int kx = 0; kx < 3; kx++) {
#pragma unroll
                for (int o = 0; o < 8; o++) {
                    float wv = sw[(o*16+ic)*9 + ky*3 + kx];
#pragma unroll
                    for (int xi = 0; xi < 4; xi++)
                        acc[o][xi] += v[2*xi + kx] * wv;
                }
            }
        }
    }
    // plane-major float4 feats: plane = im*8 + ocg*2 + h
#pragma unroll
    for (int xi = 0; xi < 4; xi++) {
        int pix = y*WFE + xb + xi;
        float4 lo = make_float4(acc[0][xi], acc[1][xi], acc[2][xi], acc[3][xi]);
        float4 hi = make_float4(acc[4][xi], acc[5][xi], acc[6][xi], acc[7][xi]);
        g_feats4[(im*8 + ocg*2 + 0)*HWF + pix] = lo;
        g_feats4[(im*8 + ocg*2 + 1)*HWF + pix] = hi;
    }
}

// ---------------- cost volume ----------------
__global__ __launch_bounds__(256) void cost_kernel() {
    int idx = blockIdx.x * blockDim.x + threadIdx.x;
    if (idx >= ND*HWF) return;
    int x = idx % WFE, y = (idx / WFE) % HFE, d = idx / HWF;
    float depth = g_depths[d];
    float xf = (float)x, yf = (float)y;
    float wgt[4][4];
    int   off[4][4];
#pragma unroll
    for (int v = 0; v < 4; v++) {
        const float* Hm = g_Hm + v*9;
        const float* bb = g_bb + v*3;
        float u  = depth*(Hm[0]*xf + Hm[1]*yf + Hm[2]) + bb[0];
        float vv = depth*(Hm[3]*xf + Hm[4]*yf + Hm[5]) + bb[1];
        float z  = depth*(Hm[6]*xf + Hm[7]*yf + Hm[8]) + bb[2];
        float valid = z > 0.001f ? 1.0f : 0.0f;
        float zc = fmaxf(z, 0.001f);
        float px = u / zc, py = vv / zc;
        float fx0 = floorf(px), fy0 = floorf(py);
        float wx = px - fx0, wy = py - fy0;
        int x0 = (int)fx0, y0 = (int)fy0;
        float w00 = (1.0f-wx)*(1.0f-wy)*valid;
        float w01 = wx*(1.0f-wy)*valid;
        float w10 = (1.0f-wx)*wy*valid;
        float w11 = wx*wy*valid;
        bool ix0 = (x0 >= 0) && (x0 < WFE);
        bool ix1 = (x0+1 >= 0) && (x0+1 < WFE);
        bool iy0 = (y0 >= 0) && (y0 < HFE);
        bool iy1 = (y0+1 >= 0) && (y0+1 < HFE);
        if (!(ix0 && iy0)) w00 = 0.0f;
        if (!(ix1 && iy0)) w01 = 0.0f;
        if (!(ix0 && iy1)) w10 = 0.0f;
        if (!(ix1 && iy1)) w11 = 0.0f;
        int cx0 = min(max(x0, 0), WFE-1), cx1 = min(max(x0+1, 0), WFE-1);
        int cy0 = min(max(y0, 0), HFE-1), cy1 = min(max(y0+1, 0), HFE-1);
        wgt[v][0] = w00; wgt[v][1] = w01; wgt[v][2] = w10; wgt[v][3] = w11;
        off[v][0] = cy0*WFE + cx0; off[v][1] = cy0*WFE + cx1;
        off[v][2] = cy1*WFE + cx0; off[v][3] = cy1*WFE + cx1;
    }
    int pix = y*WFE + x;
#pragma unroll
    for (int c4 = 0; c4 < 8; c4++) {
        float4 f0 = g_feats4[c4*HWF + pix];   // ref view plane
        float s0 = f0.x, s1 = f0.y, s2 = f0.z, s3 = f0.w;
        float q0 = f0.x*f0.x, q1 = f0.y*f0.y, q2 = f0.z*f0.z, q3 = f0.w*f0.w;
#pragma unroll
        for (int v = 0; v < 4; v++) {
            const float4* pl = g_feats4 + ((v+1)*8 + c4)*HWF;
            float4 a = pl[off[v][0]], b = pl[off[v][1]];
            float4 c = pl[off[v][2]], e = pl[off[v][3]];
            float w00 = wgt[v][0], w01 = wgt[v][1], w10 = wgt[v][2], w11 = wgt[v][3];
            float v0 = w00*a.x + w01*b.x + w10*c.x + w11*e.x;
            float v1 = w00*a.y + w01*b.y + w10*c.y + w11*e.y;
            float v2 = w00*a.z + w01*b.z + w10*c.z + w11*e.z;
            float v3 = w00*a.w + w01*b.w + w10*c.w + w11*e.w;
            s0 += v0; q0 += v0*v0;
            s1 += v1; q1 += v1*v1;
            s2 += v2; q2 += v2*v2;
            s3 += v3; q3 += v3*v3;
        }
        float m0 = s0*0.2f, m1 = s1*0.2f, m2 = s2*0.2f, m3 = s3*0.2f;
        g_cost[(((c4*4+0)*ND + d)*HFE + y)*WFE + x] = q0*0.2f - m0*m0;
        g_cost[(((c4*4+1)*ND + d)*HFE + y)*WFE + x] = q1*0.2f - m1*m1;
        g_cost[(((c4*4+2)*ND + d)*HFE + y)*WFE + x] = q2*0.2f - m2*m2;
        g_cost[(((c4*4+3)*ND + d)*HFE + y)*WFE + x] = q3*0.2f - m3*m3;
    }
}

// ---------------- reg1: smem-tiled, f32x2, vectorized LDS ----------------
// tile: D_T=4, Y_T=2, full x row (80). 160 threads = 20 xg * 2 ty * 4 td.
// s_in row layout: j = x+1 (1 front pad, 3 back pad), XSTR=84, 16B-aligned rows.
#define R1_SW_ULL 864
#define R1_XSTR 84
#define R1_ROWS 192
#define R1_IN_FLOATS (R1_ROWS*R1_XSTR)
#define R1_SMEM_BYTES (R1_SW_ULL*8 + R1_IN_FLOATS*4)

__global__ __launch_bounds__(160) void reg1_kernel(const float* __restrict__ w,
                                                   const float* __restrict__ b) {
    extern __shared__ char smem_raw[];
    unsigned long long* s_w = (unsigned long long*)smem_raw;
    float* s_in = (float*)(smem_raw + R1_SW_ULL*8);

    int tid = threadIdx.x;
    int xg = tid % 20;
    int ty = (tid / 20) % 2;
    int td = tid / 40;
    int xb = xg * 4;

    int bx = blockIdx.x;
    int y0 = (bx % (HFE/2)) * 2;
    int d0 = (bx / (HFE/2)) * 4;
    int d = d0 + td, y = y0 + ty;

    unsigned long long acc2[4][4];
#pragma unroll
    for (int op = 0; op < 4; op++) {
        unsigned long long bv = pk2(b[2*op], b[2*op+1]);
#pragma unroll
        for (int xi = 0; xi < 4; xi++) acc2[op][xi] = bv;
    }

#pragma unroll 1
    for (int ch = 0; ch < 4; ch++) {
        // weights for this ic chunk: s_w[(icl*27 + k)*4 + op] = (w[2op], w[2op+1])
        for (int e = tid; e < R1_SW_ULL; e += 160) {
            int icl = e / 108, rem = e % 108;
            int k = rem >> 2, op = rem & 3;
            int ic = ch*8 + icl;
            float lo = w[(2*op)*864 + ic*27 + k];
            float hi = w[(2*op+1)*864 + ic*27 + k];
            s_w[e] = pk2(lo, hi);
        }
        // input chunk: element-strided (conflict-free STS, coalesced LDG)
        for (int e = tid; e < R1_IN_FLOATS; e += 160) {
            int r = e / R1_XSTR, j = e % R1_XSTR;
            int icl = r / 24, rem = r % 24;
            int ddl = rem / 4, yyl = rem % 4;
            int dd = d0 - 1 + ddl, yy = y0 - 1 + yyl;
            int x = j - 1;
            bool ok = (dd >= 0) && (dd < ND) && (yy >= 0) && (yy < HFE)
                   && (x >= 0) && (x < WFE);
            s_in[e] = ok ? g_cost[(((ch*8 + icl)*ND + dd)*HFE + yy)*WFE + x] : 0.0f;
        }
        __syncthreads();

#pragma unroll 1
        for (int icl = 0; icl < 8; icl++) {
#pragma unroll
            for (int kd = 0; kd < 3; kd++) {
#pragma unroll
                for (int ky = 0; ky < 3; ky++) {
                    const float* srow = s_in + ((icl*6 + td + kd)*4 + ty + ky)*R1_XSTR;
                    float4 f0 = *(const float4*)(srow + xb);
                    float4 f1 = *(const float4*)(srow + xb + 4);
                    unsigned long long v2[6];
                    v2[0] = pk2(f0.x, f0.x); v2[1] = pk2(f0.y, f0.y);
                    v2[2] = pk2(f0.z, f0.z); v2[3] = pk2(f0.w, f0.w);
                    v2[4] = pk2(f1.x, f1.x); v2[5] = pk2(f1.y, f1.y);
                    const ulonglong2* wq =
                        (const ulonglong2*)(s_w + (icl*27 + kd*9 + ky*3)*4);
                    ulonglong2 wq0 = wq[0], wq1 = wq[1], wq2 = wq[2];
                    ulonglong2 wq3 = wq[3], wq4 = wq[4], wq5 = wq[5];
                    // kx=0: ops in wq0.x wq0.y wq1.x wq1.y ; kx=1: wq2..wq3 ; kx=2: wq4..wq5
#pragma unroll
                    for (int xi = 0; xi < 4; xi++) {
                        acc2[0][xi] = fma2(v2[xi+0], wq0.x, acc2[0][xi]);
                        acc2[1][xi] = fma2(v2[xi+0], wq0.y, acc2[1][xi]);
                        acc2[2][xi] = fma2(v2[xi+0], wq1.x, acc2[2][xi]);
                        acc2[3][xi] = fma2(v2[xi+0], wq1.y, acc2[3][xi]);
                        acc2[0][xi] = fma2(v2[xi+1], wq2.x, acc2[0][xi]);
                        acc2[1][xi] = fma2(v2[xi+1], wq2.y, acc2[1][xi]);
                        acc2[2][xi] = fma2(v2[xi+1], wq3.x, acc2[2][xi]);
                        acc2[3][xi] = fma2(v2[xi+1], wq3.y, acc2[3][xi]);
                        acc2[0][xi] = fma2(v2[xi+2], wq4.x, acc2[0][xi]);
                        acc2[1][xi] = fma2(v2[xi+2], wq4.y, acc2[1][xi]);
                        acc2[2][xi] = fma2(v2[xi+2], wq5.x, acc2[2][xi]);
                        acc2[3][xi] = fma2(v2[xi+2], wq5.y, acc2[3][xi]);
                    }
                }
            }
        }
        __syncthreads();
    }

#pragma unroll
    for (int op = 0; op < 4; op++)
#pragma unroll
        for (int xi = 0; xi < 4; xi++) {
            float lo, hi;
            upk2(lo, hi, acc2[op][xi]);
            g_reg1[(((2*op)*ND + d)*HFE + y)*WFE + xb + xi]   = fmaxf(lo, 0.0f);
            g_reg1[(((2*op+1)*ND + d)*HFE + y)*WFE + xb + xi] = fmaxf(hi, 0.0f);
        }
}

// reg2: 8 -> 1 ch, 3x3x3 SAME; thread = (d, y, 4 x)
__global__ __launch_bounds__(256) void reg2_kernel(const float* __restrict__ w,
                                                   const float* __restrict__ b) {
    __shared__ float sw[8*27];
    __shared__ float sb0;
    for (int i = threadIdx.x; i < 8*27; i += blockDim.x) sw[i] = w[i];
    if (threadIdx.x == 0) sb0 = b[0];
    __syncthreads();
    int idx = blockIdx.x * blockDim.x + threadIdx.x;
    const int XG = WFE/4;
    if (idx >= ND*HFE*XG) return;
    int xg = idx % XG, y = (idx / XG) % HFE, d = idx / (XG*HFE);
    int xb = xg * 4;
    float acc[4];
#pragma unroll
    for (int xi = 0; xi < 4; xi++) acc[xi] = sb0;
    for (int ic = 0; ic < 8; ic++) {
#pragma unroll
        for (int kd = 0; kd < 3; kd++) {
            int dd = d + kd - 1; if (dd < 0 || dd >= ND) continue;
#pragma unroll
            for (int ky = 0; ky < 3; ky++) {
                int yy = y + ky - 1; if (yy < 0 || yy >= HFE) continue;
                const float* row = g_reg1 + ((ic*ND + dd)*HFE + yy)*WFE;
                float vals[6];
#pragma unroll
                for (int j = 0; j < 6; j++) {
                    int xx = xb - 1 + j;
                    vals[j] = (xx >= 0 && xx < WFE) ? row[xx] : 0.0f;
                }
#pragma unroll
                for (int kx = 0; kx < 3; kx++) {
                    float wv = sw[ic*27 + kd*9 + ky*3 + kx];
#pragma unroll
                    for (int xi = 0; xi < 4; xi++)
                        acc[xi] += vals[kx + xi] * wv;
                }
            }
        }
    }
#pragma unroll
    for (int xi = 0; xi < 4; xi++)
        g_cost2[(d*HFE + y)*WFE + xb + xi] = acc[xi];
}

// ---------------- streaming softmax + sum4 confidence + depth regression ----------------
// thread per pixel; lanes = consecutive pixels -> coalesced; no barriers.
__global__ __launch_bounds__(256) void softmax_kernel() {
    int pix = blockIdx.x * blockDim.x + threadIdx.x;
    if (pix >= HWF) return;
    const float* col = g_cost2 + pix;
    float m = -1e30f;
#pragma unroll 8
    for (int d = 0; d < ND; d++)
        m = fmaxf(m, col[d*HWF]);
    float s = 0.0f, sd = 0.0f, mw = 0.0f;
    float e1 = 0.0f, e2 = 0.0f, e3 = 0.0f;
#pragma unroll 4
    for (int d = 0; d < ND; d++) {
        float e0 = expf(col[d*HWF] - m);
        s += e0;
        sd += e0 * g_depths[d];
        float win = e0 + e1 + e2 + e3;
        if (d >= 3) mw = fmaxf(mw, win);   // partial edge windows dominated (e>0)
        e3 = e2; e2 = e1; e1 = e0;
    }
    g_conf[pix] = mw / s;
    g_regd[pix] = sd / s;
}

// ---------------- x8 bilinear upsample ----------------
__global__ __launch_bounds__(256) void upsample_kernel(float* __restrict__ out_conf) {
    int idx = blockIdx.x * blockDim.x + threadIdx.x;
    if (idx >= HWI) return;
    int ox = idx % WIMG, oy = idx / WIMG;
    float fy = (oy + 0.5f) * ((float)HFE / HIMG) - 0.5f;
    float fx = (ox + 0.5f) * ((float)WFE / WIMG) - 0.5f;
    float y0f = floorf(fy), x0f = floorf(fx);
    float wy = fy - y0f, wx = fx - x0f;
    int y0 = (int)y0f, x0 = (int)x0f;
    int y0c = min(max(y0, 0), HFE-1), y1c = min(max(y0+1, 0), HFE-1);
    int x0c = min(max(x0, 0), WFE-1), x1c = min(max(x0+1, 0), WFE-1);
    float w00 = (1.0f-wx)*(1.0f-wy), w01 = wx*(1.0f-wy);
    float w10 = (1.0f-wx)*wy, w11 = wx*wy;
    float cv = w00*g_conf[y0c*WFE+x0c] + w01*g_conf[y0c*WFE+x1c]
             + w10*g_conf[y1c*WFE+x0c] + w11*g_conf[y1c*WFE+x1c];
    float rv = w00*g_regd[y0c*WFE+x0c] + w01*g_regd[y0c*WFE+x1c]
             + w10*g_regd[y1c*WFE+x0c] + w11*g_regd[y1c*WFE+x1c];
    out_conf[idx] = cv;
    g_regup[idx] = rv;
}

// ---------------- refinement ----------------
__global__ __launch_bounds__(256) void refine1_kernel(const float* __restrict__ img,
                                                      const float* __restrict__ w,
                                                      const float* __restrict__ b) {
    __shared__ float sw[32*4*9];
    __shared__ float sb[32];
    for (int i = threadIdx.x; i < 32*4*9; i += blockDim.x) sw[i] = w[i];
    if (threadIdx.x < 32) sb[threadIdx.x] = b[threadIdx.x];
    __syncthreads();
    int id = blockIdx.x * blockDim.x + threadIdx.x;
    const int XG = WIMG/4;
    if (id >= HIMG*XG) return;
    int ocg = blockIdx.y;
    int xg = id % XG, y = id / XG;
    int xb = xg * 4;
    float acc[16][4];
#pragma unroll
    for (int o = 0; o < 16; o++) {
        float bv = sb[ocg*16 + o];
#pragma unroll
        for (int xi = 0; xi < 4; xi++) acc[o][xi] = bv;
    }
    for (int ic = 0; ic < 4; ic++) {
        const float* src = (ic < 3) ? (img + ic*HWI) : g_regup;
#pragma unroll
        for (int ky = 0; ky < 3; ky++) {
            int yy = y + ky - 1; if (yy < 0 || yy >= HIMG) continue;
            const float* row = src + yy*WIMG;
            float vals[6];
#pragma unroll
            for (int j = 0; j < 6; j++) {
                int xx = xb - 1 + j;
                vals[j] = (xx >= 0 && xx < WIMG) ? row[xx] : 0.0f;
            }
#pragma unroll
            for (int kx = 0; kx < 3; kx++) {
#pragma unroll
                for (int o = 0; o < 16; o++) {
                    float wv = sw[(((ocg*16 + o)*4 + ic)*3 + ky)*3 + kx];
#pragma unroll
                    for (int xi = 0; xi < 4; xi++)
                        acc[o][xi] += vals[kx + xi] * wv;
                }
            }
        }
    }
    // plane-major float4 hidden: plane = ocg*4 + q
#pragma unroll
    for (int xi = 0; xi < 4; xi++) {
        int pix = y*WIMG + xb + xi;
#pragma unroll
        for (int q = 0; q < 4; q++) {
            float4 h = make_float4(fmaxf(acc[4*q+0][xi], 0.0f),
                                   fmaxf(acc[4*q+1][xi], 0.0f),
                                   fmaxf(acc[4*q+2][xi], 0.0f),
                                   fmaxf(acc[4*q+3][xi], 0.0f));
            g_hidden4[(ocg*4 + q)*HWI + pix] = h;
        }
    }
}

__global__ __launch_bounds__(256) void refine2_kernel(const float* __restrict__ w,
                                                      const float* __restrict__ b,
                                                      float* __restrict__ out_ref) {
    __shared__ float sw[32*9];
    __shared__ float sb0;
    for (int i = threadIdx.x; i < 32*9; i += blockDim.x) sw[i] = w[i];
    if (threadIdx.x == 0) sb0 = b[0];
    __syncthreads();
    int idx = blockIdx.x * blockDim.x + threadIdx.x;
    if (idx >= HWI) return;
    int x = idx % WIMG, y = idx / WIMG;
    float acc = sb0;
#pragma unroll
    for (int ky = 0; ky < 3; ky++) {
        int yy = y + ky - 1; if (yy < 0 || yy >= HIMG) continue;
#pragma unroll
        for (int kx = 0; kx < 3; kx++) {
            int xx = x + kx - 1; if (xx < 0 || xx >= WIMG) continue;
            int pix = yy*WIMG + xx;
#pragma unroll
            for (int c4 = 0; c4 < 8; c4++) {
                float4 h = g_hidden4[c4*HWI + pix];
                acc += h.x * sw[(c4*4+0)*9 + ky*3 + kx];
                acc += h.y * sw[(c4*4+1)*9 + ky*3 + kx];
                acc += h.z * sw[(c4*4+2)*9 + ky*3 + kx];
                acc += h.w * sw[(c4*4+3)*9 + ky*3 + kx];
            }
        }
    }
    out_ref[idx] = g_regup[idx] + acc;
}

// ---------------- launch ----------------
extern "C" void kernel_launch(void* const* d_in, const int* in_sizes, int n_in,
                              void* d_out, int out_size) {
    const float* images = (const float*)d_in[0];
    const float* K      = (const float*)d_in[1];
    const float* poses  = (const float*)d_in[2];
    const float* enc_w1 = (const float*)d_in[3];
    const float* enc_b1 = (const float*)d_in[4];
    const float* enc_w2 = (const float*)d_in[5];
    const float* enc_b2 = (const float*)d_in[6];
    const float* enc_w3 = (const float*)d_in[7];
    const float* enc_b3 = (const float*)d_in[8];
    const float* reg_w1 = (const float*)d_in[9];
    const float* reg_b1 = (const float*)d_in[10];
    const float* reg_w2 = (const float*)d_in[11];
    const float* reg_b2 = (const float*)d_in[12];
    const float* ref_w1 = (const float*)d_in[13];
    const float* ref_b1 = (const float*)d_in[14];
    const float* ref_w2 = (const float*)d_in[15];
    const float* ref_b2 = (const float*)d_in[16];
    float* out = (float*)d_out;

    cudaFuncSetAttribute(reg1_kernel, cudaFuncAttributeMaxDynamicSharedMemorySize,
                         R1_SMEM_BYTES);

    setup_kernel<<<1, 1>>>(K, poses);
    enc1_kernel<<<(NV*H1*W1 + 255)/256, 256>>>(images, enc_w1, enc_b1);
    enc2_kernel<<<(NV*H2*W2 + 255)/256, 256>>>(enc_w2, enc_b2);
    dim3 g3((NV*HFE*(WFE/4) + 127)/128, 4);
    enc3_kernel<<<g3, 128>>>(enc_w3, enc_b3);
    cost_kernel<<<(ND*HWF + 255)/256, 256>>>();
    reg1_kernel<<<(HFE/2)*(ND/4), 160, R1_SMEM_BYTES>>>(reg_w1, reg_b1);
    reg2_kernel<<<(ND*HFE*(WFE/4) + 255)/256, 256>>>(reg_w2, reg_b2);
    softmax_kernel<<<(HWF + 255)/256, 256>>>();
    upsample_kernel<<<(HWI + 255)/256, 256>>>(out);
    dim3 g1((HIMG*(WIMG/4) + 255)/256, 2);
    refine1_kernel<<<g1, 256>>>(images, ref_w1, ref_b1);
    refine2_kernel<<<(HWI + 255)/256, 256>>>(ref_w2, ref_b2, out + HWI);
}